// round 10
// baseline (speedup 1.0000x reference)
#include <cuda_runtime.h>

// 2 samples per CTA (named-barrier decoupled halves, best-measured DRAM%)
// + ReLU-sparsity skipping in layer 2 via predicated affine loads (R9).
//   h = relu(x[b,:] @ w1[b,:,:] + b1[b,:])   (D=128 -> H=256)
//   out = h @ w2[b,:,:] + b2[b,:]            (H=256 -> C=64)
// Rows of w2 with h[j]==0 are never loaded (~50% skipped, exact).
// The two half-blocks drift past each other's phase boundaries via
// bar.sync s,128: one half's low-MLP sparse phase overlaps the sibling's
// dense w1 streaming on the same SM, back-filling DRAM demand.

#define B_DIM 4096
#define D_DIM 128
#define H_DIM 256
#define C_DIM 64

__device__ __forceinline__ void half_bar(int s) {
    asm volatile("bar.sync %0, 128;" :: "r"(s) : "memory");
}

__global__ void __launch_bounds__(256, 5) mlp_pred2_kernel(
    const float* __restrict__ x,
    const float* __restrict__ w1,
    const float* __restrict__ b1,
    const float* __restrict__ w2,
    const float* __restrict__ b2,
    float* __restrict__ out)
{
    const int tid = threadIdx.x;
    const int s   = tid >> 7;        // 0/1: sample half
    const int l   = tid & 127;       // lane within half
    const int b   = blockIdx.x * 2 + s;

    __shared__ float  x_s[2][D_DIM];
    __shared__ float  h_s[2][H_DIM];
    __shared__ float4 part[2][128];

    // ---- stage x[b,:] ----
    x_s[s][l] = x[(size_t)b * D_DIM + l];
    half_bar(s);

    // ================= GEMV1: h[j] = sum_d x[d] * w1[d, j] =================
    // w1[b] as float4[128][64]. Thread: (dchunk = l>>6, g = l&63).
    // 64 float4 loads/thread, warp-contiguous 1024B rows. (Proven, unchanged.)
    {
        const float4* w1v = reinterpret_cast<const float4*>(
            w1 + (size_t)b * D_DIM * H_DIM);
        const int g     = l & 63;
        const int dbase = (l >> 6) * 64;

        float4 acc = make_float4(0.f, 0.f, 0.f, 0.f);
        #pragma unroll
        for (int i = 0; i < 64; ++i) {
            const int d = dbase + i;
            const float  xv = x_s[s][d];
            const float4 w  = __ldcs(&w1v[d * (H_DIM / 4) + g]);
            acc.x = fmaf(xv, w.x, acc.x);
            acc.y = fmaf(xv, w.y, acc.y);
            acc.z = fmaf(xv, w.z, acc.z);
            acc.w = fmaf(xv, w.w, acc.w);
        }
        part[s][l] = acc;
    }
    half_bar(s);

    // reduce 2 partials, add bias, ReLU -> h_s
    if (l < 64) {
        float4 s0 = part[s][l];
        float4 s1 = part[s][64 + l];
        float4 bb = reinterpret_cast<const float4*>(b1 + (size_t)b * H_DIM)[l];
        float4 h4;
        h4.x = fmaxf(s0.x + s1.x + bb.x, 0.f);
        h4.y = fmaxf(s0.y + s1.y + bb.y, 0.f);
        h4.z = fmaxf(s0.z + s1.z + bb.z, 0.f);
        h4.w = fmaxf(s0.w + s1.w + bb.w, 0.f);
        reinterpret_cast<float4*>(h_s[s])[l] = h4;
    }
    half_bar(s);

    // ========== GEMV2 (sparse via predication): ============================
    // out[c] = sum_{j: h[j]>0} h[j] * w2[j, c]
    // w2[b] as float4[256][16]. Thread: (jslot = l>>4 in 0..7, cg = l&15).
    // Row j = jslot + 8*i (affine). h[j]>0 uniform across 16-lane group:
    // predicated-off LDG is free, predicated-on loads batch freely.
    {
        const float4* w2v = reinterpret_cast<const float4*>(
            w2 + (size_t)b * H_DIM * C_DIM);
        const int cg    = l & 15;
        const int jslot = l >> 4;

        float4 acc = make_float4(0.f, 0.f, 0.f, 0.f);
        #pragma unroll 16
        for (int i = 0; i < H_DIM / 8; ++i) {
            const int j = jslot + i * 8;
            const float hv = h_s[s][j];
            if (hv > 0.f) {
                const float4 wv = __ldcs(&w2v[j * (C_DIM / 4) + cg]);
                acc.x = fmaf(hv, wv.x, acc.x);
                acc.y = fmaf(hv, wv.y, acc.y);
                acc.z = fmaf(hv, wv.z, acc.z);
                acc.w = fmaf(hv, wv.w, acc.w);
            }
        }
        part[s][l] = acc;   // index = jslot*16 + cg
    }
    half_bar(s);

    // reduce 8 jslot-partials per cg, add bias, streaming store
    if (l < 16) {
        float4 acc = part[s][l];
        #pragma unroll
        for (int k = 1; k < 8; ++k) {
            float4 p = part[s][k * 16 + l];
            acc.x += p.x; acc.y += p.y; acc.z += p.z; acc.w += p.w;
        }
        float4 bb = reinterpret_cast<const float4*>(b2 + (size_t)b * C_DIM)[l];
        acc.x += bb.x; acc.y += bb.y; acc.z += bb.z; acc.w += bb.w;
        __stcs(reinterpret_cast<float4*>(out + (size_t)b * C_DIM) + l, acc);
    }
}

extern "C" void kernel_launch(void* const* d_in, const int* in_sizes, int n_in,
                              void* d_out, int out_size)
{
    const float* x  = (const float*)d_in[0];
    const float* w1 = (const float*)d_in[1];
    const float* b1 = (const float*)d_in[2];
    const float* w2 = (const float*)d_in[3];
    const float* b2 = (const float*)d_in[4];
    float* out = (float*)d_out;

    mlp_pred2_kernel<<<B_DIM / 2, 256>>>(x, w1, b1, w2, b2, out);
}

// round 11
// speedup vs baseline: 1.0133x; 1.0133x over previous
#include <cuda_runtime.h>

// Per-sample 2-layer MLP with ReLU-sparsity skipping in layer 2 via
// predicated affine loads (R9 structure), occupancy pinned to 12 CTAs/SM.
//   h = relu(x[b,:] @ w1[b,:,:] + b1[b,:])   (D=128 -> H=256)
//   out = h @ w2[b,:,:] + b2[b,:]            (H=256 -> C=64)
// Rows of w2 with h[j]==0 contribute exactly 0 and are never loaded
// (~50% of w2 skipped, exact). h[j]>0 is uniform across each 16-lane group
// -> @P LDG with affine address: no divergence, loads batch freely.
// R11 change (single variable): __launch_bounds__(128, 12) caps regs at 40,
// restoring the 12-CTA/SM / ~68% occ point where the dense phase measured
// its best DRAM% (R6: 86.2%). R9 ran regs=48 @ 10 CTAs (occ 56.5%).

#define B_DIM 4096
#define D_DIM 128
#define H_DIM 256
#define C_DIM 64

__global__ void __launch_bounds__(128, 12) mlp_pred12_kernel(
    const float* __restrict__ x,
    const float* __restrict__ w1,
    const float* __restrict__ b1,
    const float* __restrict__ w2,
    const float* __restrict__ b2,
    float* __restrict__ out)
{
    const int l = threadIdx.x;       // 0..127
    const int b = blockIdx.x;

    __shared__ float  x_s[D_DIM];
    __shared__ float  h_s[H_DIM];
    __shared__ float4 part[128];

    // ---- stage x[b,:] ----
    x_s[l] = x[(size_t)b * D_DIM + l];
    __syncthreads();

    // ================= GEMV1: h[j] = sum_d x[d] * w1[d, j] =================
    // w1[b] as float4[128][64]. Thread: (dchunk = l>>6, g = l&63).
    // 64 float4 loads/thread, warp-contiguous 1024B rows. (Proven, unchanged.)
    {
        const float4* w1v = reinterpret_cast<const float4*>(
            w1 + (size_t)b * D_DIM * H_DIM);
        const int g     = l & 63;
        const int dbase = (l >> 6) * 64;

        float4 acc = make_float4(0.f, 0.f, 0.f, 0.f);
        #pragma unroll
        for (int i = 0; i < 64; ++i) {
            const int d = dbase + i;
            const float  xv = x_s[d];
            const float4 w  = __ldcs(&w1v[d * (H_DIM / 4) + g]);
            acc.x = fmaf(xv, w.x, acc.x);
            acc.y = fmaf(xv, w.y, acc.y);
            acc.z = fmaf(xv, w.z, acc.z);
            acc.w = fmaf(xv, w.w, acc.w);
        }
        part[l] = acc;
    }
    __syncthreads();

    // reduce 2 partials, add bias, ReLU -> h_s
    if (l < 64) {
        float4 s0 = part[l];
        float4 s1 = part[64 + l];
        float4 bb = reinterpret_cast<const float4*>(b1 + (size_t)b * H_DIM)[l];
        float4 h4;
        h4.x = fmaxf(s0.x + s1.x + bb.x, 0.f);
        h4.y = fmaxf(s0.y + s1.y + bb.y, 0.f);
        h4.z = fmaxf(s0.z + s1.z + bb.z, 0.f);
        h4.w = fmaxf(s0.w + s1.w + bb.w, 0.f);
        reinterpret_cast<float4*>(h_s)[l] = h4;
    }
    __syncthreads();

    // ========== GEMV2 (sparse via predication): ============================
    // out[c] = sum_{j: h[j]>0} h[j] * w2[j, c]
    // w2[b] as float4[256][16]. Thread: (jslot = l>>4 in 0..7, cg = l&15).
    // Row j = jslot + 8*i (affine). h_s[j] uniform across the 16-lane group:
    // predicated-off LDG is free, predicated-on loads batch freely.
    {
        const float4* w2v = reinterpret_cast<const float4*>(
            w2 + (size_t)b * H_DIM * C_DIM);
        const int cg    = l & 15;
        const int jslot = l >> 4;

        float4 acc = make_float4(0.f, 0.f, 0.f, 0.f);
        #pragma unroll 16
        for (int i = 0; i < H_DIM / 8; ++i) {
            const int j = jslot + i * 8;
            const float hv = h_s[j];
            if (hv > 0.f) {
                const float4 wv = __ldcs(&w2v[j * (C_DIM / 4) + cg]);
                acc.x = fmaf(hv, wv.x, acc.x);
                acc.y = fmaf(hv, wv.y, acc.y);
                acc.z = fmaf(hv, wv.z, acc.z);
                acc.w = fmaf(hv, wv.w, acc.w);
            }
        }
        part[l] = acc;   // index = jslot*16 + cg
    }
    __syncthreads();

    // reduce 8 jslot-partials per cg, add bias, streaming store
    if (l < 16) {
        float4 acc = part[l];
        #pragma unroll
        for (int k = 1; k < 8; ++k) {
            float4 p = part[k * 16 + l];
            acc.x += p.x; acc.y += p.y; acc.z += p.z; acc.w += p.w;
        }
        float4 bb = reinterpret_cast<const float4*>(b2 + (size_t)b * C_DIM)[l];
        acc.x += bb.x; acc.y += bb.y; acc.z += bb.z; acc.w += bb.w;
        __stcs(reinterpret_cast<float4*>(out + (size_t)b * C_DIM) + l, acc);
    }
}

extern "C" void kernel_launch(void* const* d_in, const int* in_sizes, int n_in,
                              void* d_out, int out_size)
{
    const float* x  = (const float*)d_in[0];
    const float* w1 = (const float*)d_in[1];
    const float* b1 = (const float*)d_in[2];
    const float* w2 = (const float*)d_in[3];
    const float* b2 = (const float*)d_in[4];
    float* out = (float*)d_out;

    mlp_pred12_kernel<<<B_DIM, 128>>>(x, w1, b1, w2, b2, out);
}